// round 2
// baseline (speedup 1.0000x reference)
#include <cuda_runtime.h>
#include <math.h>

// ---------------------------------------------------------------------------
// FloorPlanLoss: B=1024 batches, R=192 rooms.
//  out[0]=total, out[1]=pos_mse, out[2]=size_mse, out[3]=overlap, out[4]=adjacency
// ---------------------------------------------------------------------------

#define B 1024
#define R 192
#define ADJ_WORDS 6                  // 192 bits / 32
#define NTHREADS 256
#define NWARPS 8

__device__ unsigned int g_adjbits[R * ADJ_WORDS];
__device__ float        g_partials[B * 4];   // per-batch: mse_pos, mse_size, overlap, adjacency

// ---------------------------------------------------------------------------
// Kernel 1: build upper-triangular adjacency bitmask (i<j && adj[i][j] > 0)
// ---------------------------------------------------------------------------
__global__ void build_adjbits_kernel(const int* __restrict__ adj)
{
    int i = threadIdx.x;             // 192 threads, one row each
    if (i >= R) return;
    const int* row = adj + i * R;
    #pragma unroll
    for (int w = 0; w < ADJ_WORDS; w++) {
        unsigned bits = 0;
        int jbase = w * 32;
        #pragma unroll
        for (int k = 0; k < 32; k++) {
            int j = jbase + k;
            if (j > i && row[j] > 0) bits |= (1u << k);
        }
        g_adjbits[i * ADJ_WORDS + w] = bits;
    }
}

// ---------------------------------------------------------------------------
// Kernel 2: per-batch MSE partials + pairwise overlap / adjacency distance
// ---------------------------------------------------------------------------
__global__ __launch_bounds__(NTHREADS)
void floorplan_main_kernel(const float* __restrict__ pos,
                           const float* __restrict__ siz,
                           const float* __restrict__ tpos,
                           const float* __restrict__ tsiz)
{
    __shared__ float4   s_box[R];            // (x, x+w, y, y+h)
    __shared__ float2   s_ctr[R];            // (cx, cy)
    __shared__ unsigned s_adj[R * ADJ_WORDS];
    __shared__ float    s_red[NWARPS][4];

    const int b    = blockIdx.x;
    const int tid  = threadIdx.x;
    const int lane = tid & 31;
    const int warp = tid >> 5;

    const float* p  = pos  + b * (R * 2);
    const float* s  = siz  + b * (R * 2);
    const float* tp = tpos + b * (R * 2);
    const float* ts = tsiz + b * (R * 2);

    // --- load boxes into smem ---
    for (int r = tid; r < R; r += NTHREADS) {
        float x = p[2 * r], y = p[2 * r + 1];
        float w = s[2 * r], h = s[2 * r + 1];
        s_box[r] = make_float4(x, x + w, y, y + h);
        s_ctr[r] = make_float2(x + 0.5f * w, y + 0.5f * h);
    }
    // --- adjacency bitmask ---
    for (int k = tid; k < R * ADJ_WORDS; k += NTHREADS)
        s_adj[k] = g_adjbits[k];

    // --- MSE partial sums (this batch slice: 384 elems each) ---
    float mse_pos = 0.f, mse_size = 0.f;
    for (int k = tid; k < R * 2; k += NTHREADS) {
        float dp = p[k] - tp[k];
        float ds = s[k] - ts[k];
        mse_pos  = fmaf(dp, dp, mse_pos);
        mse_size = fmaf(ds, ds, mse_size);
    }
    __syncthreads();

    // --- pairwise loop: warp w handles rows w, w+8, ..., lanes stride j ---
    float ov = 0.f, ad = 0.f;
    for (int i = warp; i < R - 1; i += NWARPS) {
        float4 bi = s_box[i];                       // broadcast — conflict-free
        float2 ci = s_ctr[i];
        const unsigned* arow = &s_adj[i * ADJ_WORDS];
        for (int j = i + 1 + lane; j < R; j += 32) {
            float4 bj = s_box[j];
            float ow = fminf(bi.y, bj.y) - fmaxf(bi.x, bj.x);
            float oh = fminf(bi.w, bj.w) - fmaxf(bi.z, bj.z);
            ov = fmaf(fmaxf(ow, 0.f), fmaxf(oh, 0.f), ov);
            if ((arow[j >> 5] >> (j & 31)) & 1u) {
                float2 cj = s_ctr[j];
                float dx = ci.x - cj.x;
                float dy = ci.y - cj.y;
                ad += sqrtf(fmaf(dx, dx, dy * dy));
            }
        }
    }

    // --- block reduction (deterministic: fixed tree order) ---
    float v0 = mse_pos, v1 = mse_size, v2 = ov, v3 = ad;
    #pragma unroll
    for (int off = 16; off > 0; off >>= 1) {
        v0 += __shfl_xor_sync(0xffffffffu, v0, off);
        v1 += __shfl_xor_sync(0xffffffffu, v1, off);
        v2 += __shfl_xor_sync(0xffffffffu, v2, off);
        v3 += __shfl_xor_sync(0xffffffffu, v3, off);
    }
    if (lane == 0) {
        s_red[warp][0] = v0; s_red[warp][1] = v1;
        s_red[warp][2] = v2; s_red[warp][3] = v3;
    }
    __syncthreads();
    if (tid == 0) {
        float a0 = 0.f, a1 = 0.f, a2 = 0.f, a3 = 0.f;
        #pragma unroll
        for (int w = 0; w < NWARPS; w++) {
            a0 += s_red[w][0]; a1 += s_red[w][1];
            a2 += s_red[w][2]; a3 += s_red[w][3];
        }
        g_partials[b * 4 + 0] = a0;
        g_partials[b * 4 + 1] = a1;
        g_partials[b * 4 + 2] = a2;
        g_partials[b * 4 + 3] = a3;
    }
}

// ---------------------------------------------------------------------------
// Kernel 3: deterministic final reduction + loss composition
// ---------------------------------------------------------------------------
__global__ __launch_bounds__(NTHREADS)
void floorplan_finalize_kernel(float* __restrict__ out)
{
    __shared__ float s_red[NWARPS][4];
    const int tid  = threadIdx.x;
    const int lane = tid & 31;
    const int warp = tid >> 5;

    float v0 = 0.f, v1 = 0.f, v2 = 0.f, v3 = 0.f;
    for (int b = tid; b < B; b += NTHREADS) {
        v0 += g_partials[b * 4 + 0];
        v1 += g_partials[b * 4 + 1];
        v2 += g_partials[b * 4 + 2];
        v3 += g_partials[b * 4 + 3];
    }
    #pragma unroll
    for (int off = 16; off > 0; off >>= 1) {
        v0 += __shfl_xor_sync(0xffffffffu, v0, off);
        v1 += __shfl_xor_sync(0xffffffffu, v1, off);
        v2 += __shfl_xor_sync(0xffffffffu, v2, off);
        v3 += __shfl_xor_sync(0xffffffffu, v3, off);
    }
    if (lane == 0) {
        s_red[warp][0] = v0; s_red[warp][1] = v1;
        s_red[warp][2] = v2; s_red[warp][3] = v3;
    }
    __syncthreads();
    if (tid == 0) {
        float a0 = 0.f, a1 = 0.f, a2 = 0.f, a3 = 0.f;
        #pragma unroll
        for (int w = 0; w < NWARPS; w++) {
            a0 += s_red[w][0]; a1 += s_red[w][1];
            a2 += s_red[w][2]; a3 += s_red[w][3];
        }
        const float inv_mse = 1.0f / (float)(B * R * 2);   // mean over B,R,2
        const float inv_b   = 1.0f / (float)B;             // mean over batch
        float pos_loss = a0 * inv_mse;
        float siz_loss = a1 * inv_mse;
        float ov_loss  = a2 * inv_b;
        float ad_loss  = a3 * inv_b;
        float total = 1.0f * pos_loss + 1.0f * siz_loss
                    + 0.5f * ov_loss + 0.3f * ad_loss;
        out[0] = total;
        out[1] = pos_loss;
        out[2] = siz_loss;
        out[3] = ov_loss;
        out[4] = ad_loss;
    }
}

// ---------------------------------------------------------------------------
extern "C" void kernel_launch(void* const* d_in, const int* in_sizes, int n_in,
                              void* d_out, int out_size)
{
    const float* pos  = (const float*)d_in[0];   // position_updates [B,R,2]
    const float* siz  = (const float*)d_in[1];   // size_updates     [B,R,2]
    const float* tpos = (const float*)d_in[2];   // target_positions [B,R,2]
    const float* tsiz = (const float*)d_in[3];   // target_sizes     [B,R,2]
    const int*   adj  = (const int*)d_in[4];     // adjacency_matrix [1,R,R]
    float* out = (float*)d_out;

    build_adjbits_kernel<<<1, R>>>(adj);
    floorplan_main_kernel<<<B, NTHREADS>>>(pos, siz, tpos, tsiz);
    floorplan_finalize_kernel<<<1, NTHREADS>>>(out);
}

// round 3
// speedup vs baseline: 2.0350x; 2.0350x over previous
#include <cuda_runtime.h>
#include <math.h>

// ---------------------------------------------------------------------------
// FloorPlanLoss: B=1024 batches, R=192 rooms.
//  out[0]=total, out[1]=pos_mse, out[2]=size_mse, out[3]=overlap, out[4]=adjacency
// ---------------------------------------------------------------------------

#define B 1024
#define R 192
#define NTILES 6                 // 192 / 32
#define NUNITS 21                // triangular number of (tile, chunk) units
#define NTHREADS 256
#define NWARPS 8

// Transposed adjacency bitmask: g_adjT[c*192 + j] bit k set iff
//   i = 32c+k,  i < j,  adj[0][i][j] > 0
__device__ unsigned int g_adjT[NTILES * R];
__device__ float        g_partials[B * 4];
__device__ int          g_done;          // zero-init; last block resets to 0

__device__ __forceinline__ float fsqrt_approx(float x)
{
    float r;
    asm("sqrt.approx.f32 %0, %1;" : "=f"(r) : "f"(x));
    return r;
}

// ---------------------------------------------------------------------------
// Kernel 1: build transposed upper-triangular adjacency bitmask.
// grid = 6 blocks (i-chunk c), 192 threads (column j). Per k, each warp reads
// 32 consecutive j of row i=32c+k -> fully coalesced.
// ---------------------------------------------------------------------------
__global__ void build_adjT_kernel(const int* __restrict__ adj)
{
    const int c = blockIdx.x;
    const int j = threadIdx.x;
    unsigned bits = 0;
    #pragma unroll
    for (int k = 0; k < 32; k++) {
        int i = c * 32 + k;
        int v = adj[i * R + j];
        if (i < j && v > 0) bits |= (1u << k);
    }
    g_adjT[c * R + j] = bits;
}

// ---------------------------------------------------------------------------
// Work-unit tables: unit u = (tile t, i-chunk c), c <= t.
// ---------------------------------------------------------------------------
__device__ const int UT[NUNITS] = {0, 1,1, 2,2,2, 3,3,3,3, 4,4,4,4,4, 5,5,5,5,5,5};
__device__ const int UC[NUNITS] = {0, 0,1, 0,1,2, 0,1,2,3, 0,1,2,3,4, 0,1,2,3,4,5};

// ---------------------------------------------------------------------------
// Kernel 2 (fused): per-batch MSE + pairwise overlap / adjacency, plus the
// final deterministic reduction done by the last block to finish.
// ---------------------------------------------------------------------------
__global__ __launch_bounds__(NTHREADS)
void floorplan_main_kernel(const float* __restrict__ pos,
                           const float* __restrict__ siz,
                           const float* __restrict__ tpos,
                           const float* __restrict__ tsiz,
                           float* __restrict__ out)
{
    __shared__ float4 s_box[R];          // (x, x+w, y, y+h)
    __shared__ float2 s_ctr[R];          // (cx, cy)
    __shared__ float  s_red[NWARPS][4];
    __shared__ bool   s_last;

    const int b    = blockIdx.x;
    const int tid  = threadIdx.x;
    const int lane = tid & 31;
    const int warp = tid >> 5;

    const float* p  = pos  + b * (R * 2);
    const float* s  = siz  + b * (R * 2);
    const float* tp = tpos + b * (R * 2);
    const float* ts = tsiz + b * (R * 2);

    // --- load boxes into smem (float2 coalesced loads) ---
    if (tid < R) {
        float2 xy = ((const float2*)p)[tid];
        float2 wh = ((const float2*)s)[tid];
        s_box[tid] = make_float4(xy.x, xy.x + wh.x, xy.y, xy.y + wh.y);
        s_ctr[tid] = make_float2(xy.x + 0.5f * wh.x, xy.y + 0.5f * wh.y);
    }

    // --- MSE partial sums (384 elems each) ---
    float mse_pos = 0.f, mse_size = 0.f;
    for (int k = tid; k < R * 2; k += NTHREADS) {
        float dp = p[k] - tp[k];
        float ds = s[k] - ts[k];
        mse_pos  = fmaf(dp, dp, mse_pos);
        mse_size = fmaf(ds, ds, mse_size);
    }
    __syncthreads();

    // --- pairwise loop: lane owns column j (registers); broadcast row i ---
    float ov = 0.f, ad = 0.f;

    for (int u = warp; u < NUNITS; u += NWARPS) {
        const int t = UT[u];
        const int c = UC[u];
        const int j = t * 32 + lane;

        const float4 bj = s_box[j];
        const float2 cj = s_ctr[j];
        const unsigned aw = g_adjT[c * R + j];     // i<j already baked in

        const float4* bp = &s_box[c * 32];
        const float2* cp = &s_ctr[c * 32];

        if (c < t) {
            // off-diagonal chunk: every i < j, no predicate needed
            #pragma unroll
            for (int k = 0; k < 32; k++) {
                float4 bi = bp[k];                 // broadcast LDS.128
                float2 ci = cp[k];                 // broadcast LDS.64
                float ow = fminf(bi.y, bj.y) - fmaxf(bi.x, bj.x);
                float oh = fminf(bi.w, bj.w) - fmaxf(bi.z, bj.z);
                ov = fmaf(fmaxf(ow, 0.f), fmaxf(oh, 0.f), ov);
                float dx = ci.x - cj.x;
                float dy = ci.y - cj.y;
                float d  = fsqrt_approx(fmaf(dx, dx, dy * dy));
                if (aw & (1u << k)) ad += d;       // immediate-mask test
            }
        } else {
            // diagonal chunk: i = 32t+k, need k < lane for overlap
            #pragma unroll
            for (int k = 0; k < 31; k++) {
                float4 bi = bp[k];
                float2 ci = cp[k];
                float ow = fminf(bi.y, bj.y) - fmaxf(bi.x, bj.x);
                float oh = fminf(bi.w, bj.w) - fmaxf(bi.z, bj.z);
                float term = fmaxf(ow, 0.f) * fmaxf(oh, 0.f);
                if (k < lane) ov += term;
                float dx = ci.x - cj.x;
                float dy = ci.y - cj.y;
                float d  = fsqrt_approx(fmaf(dx, dx, dy * dy));
                if (aw & (1u << k)) ad += d;       // mask has i<j baked in
            }
        }
    }

    // --- block reduction (deterministic fixed tree) ---
    float v0 = mse_pos, v1 = mse_size, v2 = ov, v3 = ad;
    #pragma unroll
    for (int off = 16; off > 0; off >>= 1) {
        v0 += __shfl_xor_sync(0xffffffffu, v0, off);
        v1 += __shfl_xor_sync(0xffffffffu, v1, off);
        v2 += __shfl_xor_sync(0xffffffffu, v2, off);
        v3 += __shfl_xor_sync(0xffffffffu, v3, off);
    }
    if (lane == 0) {
        s_red[warp][0] = v0; s_red[warp][1] = v1;
        s_red[warp][2] = v2; s_red[warp][3] = v3;
    }
    __syncthreads();
    if (tid == 0) {
        float a0 = 0.f, a1 = 0.f, a2 = 0.f, a3 = 0.f;
        #pragma unroll
        for (int w = 0; w < NWARPS; w++) {
            a0 += s_red[w][0]; a1 += s_red[w][1];
            a2 += s_red[w][2]; a3 += s_red[w][3];
        }
        g_partials[b * 4 + 0] = a0;
        g_partials[b * 4 + 1] = a1;
        g_partials[b * 4 + 2] = a2;
        g_partials[b * 4 + 3] = a3;
    }

    // --- last-block-done fused finalize ---
    __threadfence();
    if (tid == 0)
        s_last = (atomicAdd(&g_done, 1) == B - 1);
    __syncthreads();
    if (!s_last) return;
    __threadfence();   // acquire: all g_partials visible

    float r0 = 0.f, r1 = 0.f, r2 = 0.f, r3 = 0.f;
    for (int bb = tid; bb < B; bb += NTHREADS) {
        r0 += g_partials[bb * 4 + 0];
        r1 += g_partials[bb * 4 + 1];
        r2 += g_partials[bb * 4 + 2];
        r3 += g_partials[bb * 4 + 3];
    }
    #pragma unroll
    for (int off = 16; off > 0; off >>= 1) {
        r0 += __shfl_xor_sync(0xffffffffu, r0, off);
        r1 += __shfl_xor_sync(0xffffffffu, r1, off);
        r2 += __shfl_xor_sync(0xffffffffu, r2, off);
        r3 += __shfl_xor_sync(0xffffffffu, r3, off);
    }
    if (lane == 0) {
        s_red[warp][0] = r0; s_red[warp][1] = r1;
        s_red[warp][2] = r2; s_red[warp][3] = r3;
    }
    __syncthreads();
    if (tid == 0) {
        float a0 = 0.f, a1 = 0.f, a2 = 0.f, a3 = 0.f;
        #pragma unroll
        for (int w = 0; w < NWARPS; w++) {
            a0 += s_red[w][0]; a1 += s_red[w][1];
            a2 += s_red[w][2]; a3 += s_red[w][3];
        }
        const float inv_mse = 1.0f / (float)(B * R * 2);
        const float inv_b   = 1.0f / (float)B;
        float pos_loss = a0 * inv_mse;
        float siz_loss = a1 * inv_mse;
        float ov_loss  = a2 * inv_b;
        float ad_loss  = a3 * inv_b;
        out[0] = pos_loss + siz_loss + 0.5f * ov_loss + 0.3f * ad_loss;
        out[1] = pos_loss;
        out[2] = siz_loss;
        out[3] = ov_loss;
        out[4] = ad_loss;
        g_done = 0;                       // restore for next graph replay
    }
}

// ---------------------------------------------------------------------------
extern "C" void kernel_launch(void* const* d_in, const int* in_sizes, int n_in,
                              void* d_out, int out_size)
{
    const float* pos  = (const float*)d_in[0];   // position_updates [B,R,2]
    const float* siz  = (const float*)d_in[1];   // size_updates     [B,R,2]
    const float* tpos = (const float*)d_in[2];   // target_positions [B,R,2]
    const float* tsiz = (const float*)d_in[3];   // target_sizes     [B,R,2]
    const int*   adj  = (const int*)d_in[4];     // adjacency_matrix [1,R,R]
    float* out = (float*)d_out;

    build_adjT_kernel<<<NTILES, R>>>(adj);
    floorplan_main_kernel<<<B, NTHREADS>>>(pos, siz, tpos, tsiz, out);
}